// round 11
// baseline (speedup 1.0000x reference)
#include <cuda_runtime.h>
#include <math.h>
#include <stdint.h>

#define N_  131072
#define D_  512
#define M_  4
#define K_  256
#define DM_ 128

// Scratch (__device__ globals are the sanctioned scratch).
__device__ float  g_xr[N_ * D_];          // 268 MB
__device__ float  g_bhi[D_ * D_];         // rotate^T hi  [n][k]
__device__ float  g_blo[D_ * D_];         // rotate^T lo  [n][k]
__device__ double g_acc[4];               // s_soft, s_hard, s_joint, s_reg

// ---------------------------------------------------------------------------
// tf32 helpers (portable PTX: cvt.rna.tf32 + mma.sync are compute_80+,
// compile fine at compute_103 — unlike tcgen05 which needs the 'a' target)
// ---------------------------------------------------------------------------
__device__ __forceinline__ void tf32split(float a, float& hi, float& lo) {
    uint32_t h;
    asm("cvt.rna.tf32.f32 %0, %1;" : "=r"(h) : "f"(a));
    hi = __uint_as_float(h);
    float l = a - hi;
    uint32_t lb;
    asm("cvt.rna.tf32.f32 %0, %1;" : "=r"(lb) : "f"(l));
    lo = __uint_as_float(lb);
}
__device__ __forceinline__ void mma8(float* d, float2 a_lo_row, float2 a_hi_row,
                                     float2 b) {
    // {a0,a1,a2,a3} = {A[r][c], A[r+8][c], A[r][c+4], A[r+8][c+4]}
    // pair-permuted smem: float2 at [row][2c] = (A[row][c], A[row][c+4])
    asm("mma.sync.aligned.m16n8k8.row.col.f32.tf32.tf32.f32 "
        "{%0,%1,%2,%3}, {%4,%5,%6,%7}, {%8,%9}, {%0,%1,%2,%3};"
        : "+f"(d[0]), "+f"(d[1]), "+f"(d[2]), "+f"(d[3])
        : "r"(__float_as_uint(a_lo_row.x)), "r"(__float_as_uint(a_hi_row.x)),
          "r"(__float_as_uint(a_lo_row.y)), "r"(__float_as_uint(a_hi_row.y)),
          "r"(__float_as_uint(b.x)), "r"(__float_as_uint(b.y)));
}

// ---------------------------------------------------------------------------
// Kernel 0: zero accumulators
// ---------------------------------------------------------------------------
__global__ void zero_acc_kernel() {
    if (threadIdx.x < 4) g_acc[threadIdx.x] = 0.0;
}

// ---------------------------------------------------------------------------
// Kernel 1a: rotate^T + tf32 split (B operand must be [n][k])
// ---------------------------------------------------------------------------
__global__ void __launch_bounds__(256) split_rot_kernel(const float* __restrict__ R)
{
    __shared__ float tile[32][33];
    const int tx = threadIdx.x & 31;
    const int ty = threadIdx.x >> 5;          // 0..7
    const int bx = blockIdx.x, by = blockIdx.y;
#pragma unroll
    for (int i = 0; i < 4; ++i)
        tile[ty + 8 * i][tx] = R[(size_t)(by * 32 + ty + 8 * i) * D_ + bx * 32 + tx];
    __syncthreads();
#pragma unroll
    for (int i = 0; i < 4; ++i) {
        const int n = bx * 32 + ty + 8 * i;
        const int k = by * 32 + tx;
        float h, l;
        tf32split(tile[tx][ty + 8 * i], h, l);
        g_bhi[(size_t)n * D_ + k] = h;
        g_blo[(size_t)n * D_ + k] = l;
    }
}

// ---------------------------------------------------------------------------
// Kernel 1b: xr = x @ rotate via mma.sync m16n8k8 3xTF32.
// Block 128x128, BK=32, 256 threads = 8 warps (4M x 2N), warp tile 32x64.
// smem pair-permutation: within each k8 group, k -> 2*(k&3) + ((k>>2)&1),
// so a thread's fragment pair (c, c+4) is one aligned LDS64; row stride 40
// makes each 16-lane phase hit all 32 banks exactly once (conflict-free).
// ---------------------------------------------------------------------------
#define AST 40
#define GEMM_SMEM (4 * 128 * AST * 4)

__global__ void __launch_bounds__(256, 1) mma_xr_kernel(const float* __restrict__ x)
{
    extern __shared__ float smf[];
    float* Ah = smf;                 // [128][40]
    float* Al = Ah + 128 * AST;
    float* Bh = Al + 128 * AST;
    float* Bl = Bh + 128 * AST;

    const int tid  = threadIdx.x;
    const int wid  = tid >> 5;
    const int lane = tid & 31;
    const int wm = wid >> 1;          // 0..3  (M)
    const int wn = wid & 1;           // 0..1  (N)
    const int qr = lane >> 2;         // 0..7
    const int qc = lane & 3;          // 0..3

    const int row  = tid >> 1;        // 0..127 (loader row)
    const int ksub = (tid & 1) * 16;  // loader k sub-chunk

    float acc[2][8][4];
#pragma unroll
    for (int mt = 0; mt < 2; ++mt)
#pragma unroll
        for (int nt = 0; nt < 8; ++nt)
#pragma unroll
            for (int e = 0; e < 4; ++e) acc[mt][nt][e] = 0.f;

    const float* apg = x + (size_t)(blockIdx.x * 128 + row) * D_;
    const float* bhg = g_bhi + (size_t)(blockIdx.y * 128 + row) * D_;
    const float* blg = g_blo + (size_t)(blockIdx.y * 128 + row) * D_;
    float* ahr = Ah + row * AST;
    float* alr = Al + row * AST;
    float* bhr = Bh + row * AST;
    float* blr = Bl + row * AST;

    for (int t = 0; t < 16; ++t) {
        const int kb = t * 32 + ksub;
        // ---- load + split A, copy B (already split), pair-permuted stores ----
#pragma unroll
        for (int j = 0; j < 4; ++j) {
            const int kk = ksub + j * 4;                    // 0..28, mult of 4
            const int base = (kk & 24) + ((kk >> 2) & 1);   // perm base
            float4 v = *(const float4*)(apg + kb + j * 4);
            float h, l;
            tf32split(v.x, h, l); ahr[base + 0] = h; alr[base + 0] = l;
            tf32split(v.y, h, l); ahr[base + 2] = h; alr[base + 2] = l;
            tf32split(v.z, h, l); ahr[base + 4] = h; alr[base + 4] = l;
            tf32split(v.w, h, l); ahr[base + 6] = h; alr[base + 6] = l;
            float4 bh = *(const float4*)(bhg + kb + j * 4);
            float4 bl = *(const float4*)(blg + kb + j * 4);
            bhr[base + 0] = bh.x; bhr[base + 2] = bh.y;
            bhr[base + 4] = bh.z; bhr[base + 6] = bh.w;
            blr[base + 0] = bl.x; blr[base + 2] = bl.y;
            blr[base + 4] = bl.z; blr[base + 6] = bl.w;
        }
        __syncthreads();

        // ---- 4 k8 steps of MMA ----
#pragma unroll
        for (int s = 0; s < 4; ++s) {
            const int kp = s * 8 + 2 * qc;
            float2 aH[2][2], aL[2][2];
#pragma unroll
            for (int mt = 0; mt < 2; ++mt) {
                const int m = wm * 32 + mt * 16 + qr;
                aH[mt][0] = *(float2*)(Ah + m * AST + kp);
                aH[mt][1] = *(float2*)(Ah + (m + 8) * AST + kp);
                aL[mt][0] = *(float2*)(Al + m * AST + kp);
                aL[mt][1] = *(float2*)(Al + (m + 8) * AST + kp);
            }
            float2 bH[8], bL[8];
#pragma unroll
            for (int nt = 0; nt < 8; ++nt) {
                const int n = wn * 64 + nt * 8 + qr;
                bH[nt] = *(float2*)(Bh + n * AST + kp);
                bL[nt] = *(float2*)(Bl + n * AST + kp);
            }
#pragma unroll
            for (int mt = 0; mt < 2; ++mt)
#pragma unroll
                for (int nt = 0; nt < 8; ++nt) {
                    mma8(acc[mt][nt], aH[mt][0], aH[mt][1], bH[nt]);  // hi*hi
                    mma8(acc[mt][nt], aH[mt][0], aH[mt][1], bL[nt]);  // hi*lo
                    mma8(acc[mt][nt], aL[mt][0], aL[mt][1], bH[nt]);  // lo*hi
                }
        }
        __syncthreads();
    }

    // ---- epilogue: write D tile ----
#pragma unroll
    for (int mt = 0; mt < 2; ++mt) {
        const int r0 = blockIdx.x * 128 + wm * 32 + mt * 16 + qr;
#pragma unroll
        for (int nt = 0; nt < 8; ++nt) {
            const int c = blockIdx.y * 128 + wn * 64 + nt * 8 + qc * 2;
            *(float2*)(g_xr + (size_t)r0 * D_ + c) =
                make_float2(acc[mt][nt][0], acc[mt][nt][1]);
            *(float2*)(g_xr + (size_t)(r0 + 8) * D_ + c) =
                make_float2(acc[mt][nt][2], acc[mt][nt][3]);
        }
    }
}

// ---------------------------------------------------------------------------
// Kernel 2: distances/softmax/argmax/losses.  (UNCHANGED from R7 — bit-frozen)
// ---------------------------------------------------------------------------
#define CBT_S   258
#define SP_S    36
#define DT_S    258
#define GROUP   32
#define TILE_N  128
#define CUT     20.0f

#define SMEM_FLOATS (128*CBT_S + 256 + 128*SP_S + GROUP*DT_S + GROUP*256 + 32)
#define SMEM_BYTES  (SMEM_FLOATS * 4)

__device__ __forceinline__ void ffma2(unsigned long long& d,
                                      unsigned long long a,
                                      unsigned long long b) {
    asm("fma.rn.f32x2 %0, %1, %2, %0;" : "+l"(d) : "l"(a), "l"(b));
}
__device__ __forceinline__ unsigned long long dup2(float x) {
    unsigned long long r;
    asm("mov.b64 %0, {%1, %2};" : "=l"(r) : "f"(x), "f"(x));
    return r;
}
__device__ __forceinline__ float2 unpk2(unsigned long long v) {
    float2 f;
    asm("mov.b64 {%0, %1}, %2;" : "=f"(f.x), "=f"(f.y) : "l"(v));
    return f;
}
__device__ __forceinline__ unsigned fmap(float f) {
    unsigned b = __float_as_uint(f);
    return (b & 0x80000000u) ? ~b : (b | 0x80000000u);
}
__device__ __forceinline__ float funmap(unsigned u) {
    unsigned b = (u & 0x80000000u) ? (u & 0x7FFFFFFFu) : ~u;
    return __uint_as_float(b);
}

__global__ void __launch_bounds__(256) dist_kernel(
    const float* __restrict__ cb, float* __restrict__ out)
{
    extern __shared__ float sm[];
    float* cbT = sm;                         // [128][258] d-major codebook
    float* c2s = cbT + 128 * CBT_S;          // [256]
    float* sps = c2s + 256;                  // [128][36]  sp interleaved by row
    float* dts = sps + 128 * SP_S;           // [32][258]  xc rows / e-list
    int*   kix = (int*)(dts + GROUP * DT_S); // [32][256]  candidate k indices
    float* red = (float*)(kix + GROUP * 256);// [32]

    const int m    = blockIdx.y;
    const int tid  = threadIdx.x;
    const int lane = tid & 31;
    const int warp = tid >> 5;

    {
        const float* cbm = cb + (size_t)m * K_ * DM_;
        const int k = tid;
        float c2 = 0.f;
#pragma unroll 8
        for (int dg = 0; dg < 32; ++dg) {
            float4 v = *(const float4*)(cbm + (size_t)k * DM_ + dg * 4);
            cbT[(dg * 4 + 0) * CBT_S + k] = v.x;
            cbT[(dg * 4 + 1) * CBT_S + k] = v.y;
            cbT[(dg * 4 + 2) * CBT_S + k] = v.z;
            cbT[(dg * 4 + 3) * CBT_S + k] = v.w;
            c2 = fmaf(v.x, v.x, c2); c2 = fmaf(v.y, v.y, c2);
            c2 = fmaf(v.z, v.z, c2); c2 = fmaf(v.w, v.w, c2);
        }
        c2s[k] = c2;
    }
    __syncthreads();

    const int kp = tid & 127;
    const int k0 = kp * 2;
    const int rh = tid >> 7;
    const int nbase = blockIdx.x * TILE_N;

    float la = 0.f, lb = 0.f, lc = 0.f;

    for (int g = 0; g < TILE_N / GROUP; ++g) {
        const int n0 = nbase + g * GROUP;

        {
            const int j  = tid & 31;
            const int dg = tid >> 5;
            const float* src = g_xr + (size_t)(n0 + j) * D_ + m * DM_ + dg * 16;
            float4 v0 = *(const float4*)(src);
            float4 v1 = *(const float4*)(src + 4);
            float4 v2 = *(const float4*)(src + 8);
            float4 v3 = *(const float4*)(src + 12);
            const int b = dg * 16 * SP_S + j;
            sps[b +  0 * SP_S] = v0.x; sps[b +  1 * SP_S] = v0.y;
            sps[b +  2 * SP_S] = v0.z; sps[b +  3 * SP_S] = v0.w;
            sps[b +  4 * SP_S] = v1.x; sps[b +  5 * SP_S] = v1.y;
            sps[b +  6 * SP_S] = v1.z; sps[b +  7 * SP_S] = v1.w;
            sps[b +  8 * SP_S] = v2.x; sps[b +  9 * SP_S] = v2.y;
            sps[b + 10 * SP_S] = v2.z; sps[b + 11 * SP_S] = v2.w;
            sps[b + 12 * SP_S] = v3.x; sps[b + 13 * SP_S] = v3.y;
            sps[b + 14 * SP_S] = v3.z; sps[b + 15 * SP_S] = v3.w;
        }
        __syncthreads();

        unsigned long long acc0[8], acc1[8];
#pragma unroll
        for (int i = 0; i < 8; ++i) { acc0[i] = 0ULL; acc1[i] = 0ULL; }

#pragma unroll 2
        for (int d = 0; d < DM_; ++d) {
            unsigned long long cpair =
                *(const unsigned long long*)(cbT + d * CBT_S + k0);
            float2 cf = unpk2(cpair);
            unsigned long long c0d = dup2(cf.x);
            unsigned long long c1d = dup2(cf.y);
            const ulonglong2* sp2 =
                (const ulonglong2*)(sps + d * SP_S + rh * 16);
            ulonglong2 sA = sp2[0];
            ulonglong2 sB = sp2[1];
            ffma2(acc0[0], c0d, sA.x); ffma2(acc0[1], c0d, sA.y);
            ffma2(acc0[2], c0d, sB.x); ffma2(acc0[3], c0d, sB.y);
            ffma2(acc1[0], c1d, sA.x); ffma2(acc1[1], c1d, sA.y);
            ffma2(acc1[2], c1d, sB.x); ffma2(acc1[3], c1d, sB.y);
            ulonglong2 sC = sp2[2];
            ulonglong2 sD = sp2[3];
            ffma2(acc0[4], c0d, sC.x); ffma2(acc0[5], c0d, sC.y);
            ffma2(acc0[6], c0d, sD.x); ffma2(acc0[7], c0d, sD.y);
            ffma2(acc1[4], c1d, sC.x); ffma2(acc1[5], c1d, sC.y);
            ffma2(acc1[6], c1d, sD.x); ffma2(acc1[7], c1d, sD.y);
        }
#pragma unroll
        for (int p = 0; p < 8; ++p) {
            float2 a = unpk2(acc0[p]);
            float2 b = unpk2(acc1[p]);
            const int r = rh * 16 + 2 * p;
            *(float2*)&dts[(size_t)r * DT_S + k0]       = make_float2(a.x, b.x);
            *(float2*)&dts[(size_t)(r + 1) * DT_S + k0] = make_float2(a.y, b.y);
        }
        __syncthreads();

        for (int rr = 0; rr < 4; ++rr) {
            const int r = warp * 4 + rr;
            float* drow = dts + (size_t)r * DT_S;

            float v = 0.f;
#pragma unroll
            for (int d = lane; d < DM_; d += 32) {
                float s = sps[d * SP_S + r];
                v = fmaf(s, s, v);
            }
#pragma unroll
            for (int off = 16; off; off >>= 1)
                v += __shfl_down_sync(0xffffffffu, v, off);
            const float x2v = __shfl_sync(0xffffffffu, v, 0);

            float dv[8];
#pragma unroll
            for (int i = 0; i < 8; ++i) {
                const int k = lane + 32 * i;
                dv[i] = x2v - 2.f * drow[k] + c2s[k];
            }

            float mn = dv[0]; int mk = lane;
#pragma unroll
            for (int i = 1; i < 8; ++i)
                if (dv[i] < mn) { mn = dv[i]; mk = lane + 32 * i; }

            unsigned long long key =
                ((unsigned long long)fmap(mn) << 32) | (unsigned)mk;
#pragma unroll
            for (int off = 16; off; off >>= 1) {
                unsigned long long o = __shfl_down_sync(0xffffffffu, key, off);
                if (o < key) key = o;
            }
            key = __shfl_sync(0xffffffffu, key, 0);
            const int   kh   = (int)(key & 0xffffffffu);
            const float dmin = funmap((unsigned)(key >> 32));
            if (lane == 0)
                out[(size_t)(n0 + r) * M_ + m] = (float)kh;

            float esum = 0.f;
            int base = 0;
#pragma unroll
            for (int i = 0; i < 8; ++i) {
                const float diff = dv[i] - dmin;
                const bool f = diff < CUT;
                const float e = f ? __expf(-diff) : 0.f;
                esum += e;
                const unsigned bal = __ballot_sync(0xffffffffu, f);
                if (f) {
                    const int pos = base + __popc(bal & ((1u << lane) - 1u));
                    drow[pos] = e;
                    kix[r * 256 + pos] = lane + 32 * i;
                }
                base += __popc(bal);
            }
#pragma unroll
            for (int off = 16; off; off >>= 1)
                esum += __shfl_xor_sync(0xffffffffu, esum, off);
            const float inv = 1.f / esum;
            const int nnz = base;
            __syncwarp();

            float s0 = 0.f, s1 = 0.f, s2 = 0.f, s3 = 0.f;
            for (int s = 0; s < nnz; ++s) {
                const float p = drow[s] * inv;
                const float* cc = cbT + kix[r * 256 + s];
                s0 = fmaf(p, cc[(size_t)lane * CBT_S], s0);
                s1 = fmaf(p, cc[(size_t)(lane + 32) * CBT_S], s1);
                s2 = fmaf(p, cc[(size_t)(lane + 64) * CBT_S], s2);
                s3 = fmaf(p, cc[(size_t)(lane + 96) * CBT_S], s3);
            }

            const float* ch = cbT + kh;
            const float so[4] = {s0, s1, s2, s3};
#pragma unroll
            for (int i = 0; i < 4; ++i) {
                const int d = lane + 32 * i;
                const float sp = sps[d * SP_S + r];
                const float h  = ch[(size_t)d * CBT_S];
                const float u = sp - so[i]; la = fmaf(u, u, la);
                const float vv = sp - h;    lb = fmaf(vv, vv, lb);
                const float w = so[i] - h;  lc = fmaf(w, w, lc);
            }
        }
        __syncthreads();
    }

#pragma unroll
    for (int off = 16; off; off >>= 1) {
        la += __shfl_down_sync(0xffffffffu, la, off);
        lb += __shfl_down_sync(0xffffffffu, lb, off);
        lc += __shfl_down_sync(0xffffffffu, lc, off);
    }
    if (lane == 0) { red[warp] = la; red[8 + warp] = lb; red[16 + warp] = lc; }
    __syncthreads();
    if (tid == 0) {
        float a1 = 0.f, a2 = 0.f, a3 = 0.f;
#pragma unroll
        for (int w = 0; w < 8; ++w) {
            a1 += red[w]; a2 += red[8 + w]; a3 += red[16 + w];
        }
        atomicAdd(&g_acc[0], (double)a1);
        atomicAdd(&g_acc[1], (double)a2);
        atomicAdd(&g_acc[2], (double)a3);
    }
}

// ---------------------------------------------------------------------------
// Kernel 3: reg = sum (R R^T - I)^2   (unchanged)
// ---------------------------------------------------------------------------
__global__ void __launch_bounds__(256) reg_kernel(const float* __restrict__ R)
{
    __shared__ float  ri[8][D_];
    __shared__ double dred[256];
    const int i0 = blockIdx.x * 8;
    const int j  = blockIdx.y * 256 + threadIdx.x;

    for (int idx = threadIdx.x; idx < 8 * D_; idx += 256)
        ri[idx >> 9][idx & 511] = R[(size_t)(i0 + (idx >> 9)) * D_ + (idx & 511)];
    __syncthreads();

    const float4* rj = (const float4*)(R + (size_t)j * D_);
    float acc[8];
#pragma unroll
    for (int i = 0; i < 8; ++i) acc[i] = 0.f;
    for (int k4 = 0; k4 < D_ / 4; ++k4) {
        float4 b = __ldg(&rj[k4]);
#pragma unroll
        for (int i = 0; i < 8; ++i) {
            acc[i] = fmaf(ri[i][k4 * 4 + 0], b.x, acc[i]);
            acc[i] = fmaf(ri[i][k4 * 4 + 1], b.y, acc[i]);
            acc[i] = fmaf(ri[i][k4 * 4 + 2], b.z, acc[i]);
            acc[i] = fmaf(ri[i][k4 * 4 + 3], b.w, acc[i]);
        }
    }
    double local = 0.0;
#pragma unroll
    for (int i = 0; i < 8; ++i) {
        float gv = acc[i] - ((i0 + i) == j ? 1.f : 0.f);
        local += (double)gv * (double)gv;
    }
    dred[threadIdx.x] = local;
    __syncthreads();
    for (int s = 128; s > 0; s >>= 1) {
        if (threadIdx.x < s) dred[threadIdx.x] += dred[threadIdx.x + s];
        __syncthreads();
    }
    if (threadIdx.x == 0) atomicAdd(&g_acc[3], dred[0]);
}

// ---------------------------------------------------------------------------
// Kernel 4: finalize loss (unchanged)
// ---------------------------------------------------------------------------
__global__ void finalize_kernel(float* __restrict__ out)
{
    if (threadIdx.x == 0) {
        const double invA = 1.0 / ((double)N_ * (double)DM_);
        double loss = 0.1 * (g_acc[0] * invA)
                    +       (g_acc[1] * invA)
                    + 0.1 * (g_acc[2] * invA)
                    + 0.01 * (g_acc[3] / ((double)D_ * (double)D_));
        out[(size_t)N_ * M_] = (float)loss;
    }
}

// ---------------------------------------------------------------------------
extern "C" void kernel_launch(void* const* d_in, const int* in_sizes, int n_in,
                              void* d_out, int out_size)
{
    const float* x   = nullptr;
    const float* cbk = nullptr;
    const float* rot = nullptr;
    for (int i = 0; i < n_in; ++i) {
        if (in_sizes[i] == N_ * D_)            x   = (const float*)d_in[i];
        else if (in_sizes[i] == M_ * K_ * DM_) cbk = (const float*)d_in[i];
        else if (in_sizes[i] == D_ * D_)       rot = (const float*)d_in[i];
    }
    if (!x)   x   = (const float*)d_in[0];
    if (!cbk) cbk = (const float*)d_in[1];
    if (!rot) rot = (const float*)d_in[2];

    float* out = (float*)d_out;

    cudaFuncSetAttribute(dist_kernel,
                         cudaFuncAttributeMaxDynamicSharedMemorySize, SMEM_BYTES);
    cudaFuncSetAttribute(mma_xr_kernel,
                         cudaFuncAttributeMaxDynamicSharedMemorySize, GEMM_SMEM);

    zero_acc_kernel<<<1, 32>>>();
    split_rot_kernel<<<dim3(16, 16), 256>>>(rot);
    mma_xr_kernel<<<dim3(N_ / 128, D_ / 128), 256, GEMM_SMEM>>>(x);
    dist_kernel<<<dim3(N_ / TILE_N, M_), 256, SMEM_BYTES>>>(cbk, out);
    reg_kernel<<<dim3(D_ / 8, 2), 256>>>(rot);
    if (out_size > N_ * M_) finalize_kernel<<<1, 32>>>(out);
}